// round 3
// baseline (speedup 1.0000x reference)
#include <cuda_runtime.h>

typedef unsigned long long u64;

#define C_DIM 64
#define K_DIM 512
#define N_PTS 262144      // B*H*W
#define HW_SZ 4096

// float32 concat output layout (reference return order):
// out[16777216], diff[1], embedding_ind[262144], new_embedding[32768],
// new_cluster_size[512], new_embedding_avg[32768]
#define OFF_OUT  0
#define OFF_DIFF 16777216
#define OFF_IND  16777217
#define OFF_EMB  17039361
#define OFF_NCS  17072129
#define OFF_AVG  17072641

__device__ float g_esum[C_DIM * K_DIM];  // segment_sum accumulator [C][K]
__device__ int   g_counts[K_DIM];
__device__ float g_diff;
__device__ float g_ee[K_DIM];            // ||e_k||^2

__device__ __forceinline__ u64 ffma2(u64 a, u64 b, u64 c) {
    u64 d;
    asm("fma.rn.f32x2 %0, %1, %2, %3;" : "=l"(d) : "l"(a), "l"(b), "l"(c));
    return d;
}
__device__ __forceinline__ u64 fadd2(u64 a, u64 b) {
    u64 d;
    asm("add.rn.f32x2 %0, %1, %2;" : "=l"(d) : "l"(a), "l"(b));
    return d;
}

// ---------------- init: zero scratch + ||e_k||^2 (merged) ----------------
__global__ void k_init(const float* __restrict__ E) {
    int i = blockIdx.x * 256 + threadIdx.x;     // grid 130 x 256
    if (i < C_DIM * K_DIM) g_esum[i] = 0.0f;
    int j = i - C_DIM * K_DIM;
    if (j >= 0 && j < K_DIM) g_counts[j] = 0;
    if (i == 0) g_diff = 0.0f;
    if (i < K_DIM) {
        float s = 0.0f;
#pragma unroll
        for (int c = 0; c < C_DIM; c++) {
            float v = E[c * K_DIM + i];
            s = fmaf(v, v, s);
        }
        g_ee[i] = s;
    }
}

// ---------------- main: argmin + quantize + diff + EMA scatter ----------------
// 128 threads/CTA, 2 points/thread (f32x2 packed), 256 points/CTA, grid 1024.
// smem: code chunk of 128 codes, duplicated pairs, row = 33 ulonglong2 (padded,
// 16B-aligned rows for broadcast LDS.128).
__global__ void __launch_bounds__(128, 2)
k_main(const float* __restrict__ in, const float* __restrict__ E,
       float* __restrict__ outf) {
    extern __shared__ u64 smem_raw[];
    ulonglong2* se4 = (ulonglong2*)smem_raw;   // [128][33] ull2 (=[128][66] float2)
    float2*     se2 = (float2*)smem_raw;

    const int tid = threadIdx.x;
    const int n0  = blockIdx.x * 256 + tid * 2;   // even point index
    const int b   = n0 >> 12;
    const int hw  = n0 & 4095;                    // even

    // load this thread's 2 points, packed per-channel as f32x2 (64 LDG.64, coalesced)
    const u64* __restrict__ xin = (const u64*)(in + (size_t)b * 262144 + hw);
    u64 x2[C_DIM];
#pragma unroll
    for (int c = 0; c < C_DIM; c++) x2[c] = xin[c * 2048];

    u64 xx2 = 0ULL;
#pragma unroll
    for (int c = 0; c < C_DIM; c++) xx2 = ffma2(x2[c], x2[c], xx2);

    float best0 = 3.4e38f, best1 = 3.4e38f;
    int   bi0 = 0, bi1 = 0;
    const u64 NEG2 = 0xC0000000C0000000ULL;   // {-2.0f, -2.0f}

    for (int chunk = 0; chunk < 4; ++chunk) {
        const int kc0 = chunk * 128;
        __syncthreads();
        // stage 128 codes: fill all 64 channels (dup pairs), coalesced E reads
        for (int idx = tid; idx < 128 * C_DIM; idx += 128) {
            int c = idx >> 7, k = idx & 127;
            float v = E[c * K_DIM + kc0 + k];
            se2[k * 66 + c] = make_float2(v, v);
        }
        __syncthreads();

        for (int kq = 0; kq < 128; kq += 8) {
            u64 acc[8];
#pragma unroll
            for (int q = 0; q < 8; q++) acc[q] = 0ULL;

#pragma unroll
            for (int c = 0; c < C_DIM; c += 2) {
#pragma unroll
                for (int q = 0; q < 8; q++) {
                    ulonglong2 ev = se4[(kq + q) * 33 + (c >> 1)];  // broadcast LDS.128
                    acc[q] = ffma2(x2[c],     ev.x, acc[q]);
                    acc[q] = ffma2(x2[c + 1], ev.y, acc[q]);
                }
            }
#pragma unroll
            for (int q = 0; q < 8; q++) {
                int   kg  = kc0 + kq + q;
                float eev = g_ee[kg];
                u64 ee2;
                asm("mov.b64 %0, {%1, %1};" : "=l"(ee2) : "f"(eev));
                u64 s2 = ffma2(acc[q], NEG2, fadd2(xx2, ee2));
                float s0, s1;
                asm("mov.b64 {%0, %1}, %2;" : "=f"(s0), "=f"(s1) : "l"(s2));
                if (s0 < best0) { best0 = s0; bi0 = kg; }
                if (s1 < best1) { best1 = s1; bi1 = kg; }
            }
        }
    }

    // ---- fused epilogue: quantize_st output, diff partial, segment_sum, counts ----
    float* __restrict__ outp = outf + OFF_OUT + (size_t)b * 262144 + hw;
    const float* __restrict__ Eb0 = E + bi0;
    const float* __restrict__ Eb1 = E + bi1;
    float dsum = 0.0f;
#pragma unroll 4
    for (int c = 0; c < C_DIM; c++) {
        float xv0, xv1;
        asm("mov.b64 {%0, %1}, %2;" : "=f"(xv0), "=f"(xv1) : "l"(x2[c]));
        float q0 = Eb0[(size_t)c * K_DIM];
        float q1 = Eb1[(size_t)c * K_DIM];
        float t0 = q0 - xv0, t1 = q1 - xv1;           // stop_grad(quantize - x)
        float2 o = make_float2(xv0 + t0, xv1 + t1);   // x + (q - x), matching ref rounding
        *(float2*)(outp + (size_t)c * 4096) = o;
        dsum = fmaf(t0, t0, dsum);
        dsum = fmaf(t1, t1, dsum);
        atomicAdd(&g_esum[c * K_DIM + bi0], xv0);
        atomicAdd(&g_esum[c * K_DIM + bi1], xv1);
    }
    atomicAdd(&g_counts[bi0], 1);
    atomicAdd(&g_counts[bi1], 1);

    // embedding_ind as float (offset is odd -> scalar stores)
    outf[OFF_IND + n0]     = (float)bi0;
    outf[OFF_IND + n0 + 1] = (float)bi1;

    // diff block reduction
    __syncthreads();
    float* red = (float*)smem_raw;
#pragma unroll
    for (int o = 16; o; o >>= 1) dsum += __shfl_down_sync(0xffffffffu, dsum, o);
    if ((tid & 31) == 0) red[tid >> 5] = dsum;
    __syncthreads();
    if (tid == 0) {
        atomicAdd(&g_diff, red[0] + red[1] + red[2] + red[3]);
    }
}

// ---------------- final: EMA normalization + small outputs ----------------
__global__ void k_final(const float* __restrict__ cs_in,
                        const float* __restrict__ avg_in,
                        float* __restrict__ outf) {
    __shared__ float sm[512];
    int t = threadIdx.x;   // 512 threads
    float cnt = (float)g_counts[t];
    float ncs = cs_in[t] * 0.99f + 0.01f * cnt;
    outf[OFF_NCS + t] = ncs;
    sm[t] = ncs;
    __syncthreads();
#pragma unroll
    for (int s = 256; s > 0; s >>= 1) {
        if (t < s) sm[t] += sm[t + s];
        __syncthreads();
    }
    float n  = sm[0];
    float cs = (ncs + 1e-5f) / (n + 0.00512f) * n;
    for (int c = 0; c < C_DIM; c++) {
        float av = avg_in[c * K_DIM + t] * 0.99f + 0.01f * g_esum[c * K_DIM + t];
        outf[OFF_AVG + c * K_DIM + t] = av;
        outf[OFF_EMB + c * K_DIM + t] = av / cs;
    }
    if (t == 0) outf[OFF_DIFF] = g_diff * (1.0f / 16777216.0f);
}

extern "C" void kernel_launch(void* const* d_in, const int* in_sizes, int n_in,
                              void* d_out, int out_size) {
    // Defensive size-based resolution where unambiguous (dict order assumed
    // for the two [C,K] buffers: embedding before embedding_avg).
    const float* in    = (const float*)d_in[0];  // input  [B,C,H,W] (16777216)
    const float* E     = (const float*)d_in[1];  // embedding [C,K]  (32768)
    const float* csize = (const float*)d_in[2];  // cluster_size [K] (512)
    const float* eavg  = (const float*)d_in[3];  // embedding_avg [C,K] (32768)
    {
        const float* p32k[2] = {nullptr, nullptr};
        int n32k = 0;
        for (int i = 0; i < n_in; i++) {
            if (in_sizes[i] == N_PTS * C_DIM) in = (const float*)d_in[i];
            else if (in_sizes[i] == K_DIM)    csize = (const float*)d_in[i];
            else if (in_sizes[i] == C_DIM * K_DIM && n32k < 2)
                p32k[n32k++] = (const float*)d_in[i];
        }
        if (n32k == 2) { E = p32k[0]; eavg = p32k[1]; }
    }
    float* outf = (float*)d_out;

    cudaFuncSetAttribute(k_main, cudaFuncAttributeMaxDynamicSharedMemorySize, 69632);

    k_init<<<130, 256>>>(E);
    k_main<<<1024, 128, 128 * 33 * sizeof(ulonglong2)>>>(in, E, outf);
    k_final<<<1, 512>>>(csize, eavg, outf);
}

// round 7
// speedup vs baseline: 1.2680x; 1.2680x over previous
#include <cuda_runtime.h>
#include <float.h>

typedef unsigned long long u64;

#define C_DIM 64
#define K_DIM 512
#define N_PTS 262144      // B*H*W

// float32 concat output layout (reference return order):
// out[16777216], diff[1], embedding_ind[262144], new_embedding[32768],
// new_cluster_size[512], new_embedding_avg[32768]
#define OFF_OUT  0
#define OFF_DIFF 16777216
#define OFF_IND  16777217
#define OFF_EMB  17039361
#define OFF_NCS  17072129
#define OFF_AVG  17072641

// Scratch: zero at module load; k_final re-zeroes after reading, so every
// kernel_launch call sees zeros (graph-replay safe, deterministic).
__device__ float g_esum[C_DIM * K_DIM];  // segment_sum accumulator [C][K]
__device__ int   g_counts[K_DIM];
__device__ float g_diff;

__device__ __forceinline__ u64 ffma2(u64 a, u64 b, u64 c) {
    u64 d;
    asm("fma.rn.f32x2 %0, %1, %2, %3;" : "=l"(d) : "l"(a), "l"(b), "l"(c));
    return d;
}

// ---------------- main: argmin + quantize + diff + EMA scatter ----------------
// 128 threads/CTA, 1 point/thread, channels packed f32x2 (32 u64 regs).
// grid 2048, 4 CTAs/SM target (16 warps/SM).
// smem: 128-code chunk, rows of 68 floats (272B, 16B-aligned) + ee[512].
__global__ void __launch_bounds__(128, 4)
k_main(const float* __restrict__ in, const float* __restrict__ E,
       float* __restrict__ outf) {
    extern __shared__ float sefl[];              // [128*68] codes, then ee[512]
    ulonglong2* se4 = (ulonglong2*)sefl;         // row stride 17 ull2
    float* see = sefl + 128 * 68;                // ||e_k||^2

    const int tid = threadIdx.x;
    const int n0  = blockIdx.x * 128 + tid;      // point index
    const int b   = n0 >> 12;
    const int hw  = n0 & 4095;

    // ---- load this thread's point: 64 channels as 32 f32x2 (coalesced LDG.32) ----
    const float* __restrict__ xin = in + (size_t)b * 262144 + hw;
    u64 x2[32];
#pragma unroll
    for (int j = 0; j < 32; j++) {
        float a0 = xin[(size_t)(2 * j)     * 4096];
        float a1 = xin[(size_t)(2 * j + 1) * 4096];
        asm("mov.b64 %0, {%1, %2};" : "=l"(x2[j]) : "f"(a0), "f"(a1));
    }
    u64 xs = 0ULL;
#pragma unroll
    for (int j = 0; j < 32; j++) xs = ffma2(x2[j], x2[j], xs);
    float xlo, xhi;
    asm("mov.b64 {%0, %1}, %2;" : "=f"(xlo), "=f"(xhi) : "l"(xs));
    const float xx = xlo + xhi;

    // ---- per-CTA ||e_k||^2 into smem (covered by first chunk's barrier) ----
    for (int k = tid; k < K_DIM; k += 128) {
        float s = 0.0f;
#pragma unroll
        for (int c = 0; c < C_DIM; c++) {
            float v = E[c * K_DIM + k];
            s = fmaf(v, v, s);
        }
        see[k] = s;
    }

    float best = FLT_MAX;
    int   bi   = 0;

    for (int chunk = 0; chunk < 4; ++chunk) {
        const int kc0 = chunk * 128;
        __syncthreads();
        // stage 128 codes x 64 channels (coalesced E reads; rows of 68 floats)
        for (int idx = tid; idx < 128 * C_DIM; idx += 128) {
            int c = idx >> 7, k = idx & 127;
            sefl[k * 68 + c] = E[c * K_DIM + kc0 + k];
        }
        __syncthreads();

        for (int kq = 0; kq < 128; kq += 4) {
            u64 acc[4];
#pragma unroll
            for (int q = 0; q < 4; q++) acc[q] = 0ULL;

#pragma unroll
            for (int cq = 0; cq < 16; cq++) {      // 4 channels per iter
#pragma unroll
                for (int q = 0; q < 4; q++) {
                    ulonglong2 ev = se4[(kq + q) * 17 + cq];  // broadcast LDS.128
                    acc[q] = ffma2(x2[2 * cq],     ev.x, acc[q]);
                    acc[q] = ffma2(x2[2 * cq + 1], ev.y, acc[q]);
                }
            }
#pragma unroll
            for (int q = 0; q < 4; q++) {
                float lo, hi;
                asm("mov.b64 {%0, %1}, %2;" : "=f"(lo), "=f"(hi) : "l"(acc[q]));
                float s = lo + hi;
                int   kg = kc0 + kq + q;
                float d  = fmaf(-2.0f, s, xx) + see[kg];   // (xx - 2 dot) + ee
                if (d < best) { best = d; bi = kg; }
            }
        }
    }

    // ---- fused epilogue: quantize_st output, diff partial, segment_sum, counts ----
    float* __restrict__ outp = outf + OFF_OUT + (size_t)b * 262144 + hw;
    const float* __restrict__ Eb = E + bi;
    float dsum = 0.0f;
#pragma unroll 4
    for (int j = 0; j < 32; j++) {
        float xv0, xv1;
        asm("mov.b64 {%0, %1}, %2;" : "=f"(xv0), "=f"(xv1) : "l"(x2[j]));
        int c0 = 2 * j, c1 = 2 * j + 1;
        float q0 = Eb[(size_t)c0 * K_DIM];
        float q1 = Eb[(size_t)c1 * K_DIM];
        float t0 = q0 - xv0, t1 = q1 - xv1;        // stop_grad(quantize - x)
        outp[(size_t)c0 * 4096] = xv0 + t0;        // x + (q - x), ref rounding
        outp[(size_t)c1 * 4096] = xv1 + t1;
        dsum = fmaf(t0, t0, dsum);
        dsum = fmaf(t1, t1, dsum);
        atomicAdd(&g_esum[c0 * K_DIM + bi], xv0);
        atomicAdd(&g_esum[c1 * K_DIM + bi], xv1);
    }
    atomicAdd(&g_counts[bi], 1);
    outf[OFF_IND + n0] = (float)bi;

    // diff block reduction (4 warps)
    __syncthreads();
#pragma unroll
    for (int o = 16; o; o >>= 1) dsum += __shfl_down_sync(0xffffffffu, dsum, o);
    if ((tid & 31) == 0) sefl[tid >> 5] = dsum;
    __syncthreads();
    if (tid == 0)
        atomicAdd(&g_diff, sefl[0] + sefl[1] + sefl[2] + sefl[3]);
}

// ---------------- final: EMA normalization + small outputs + re-zero scratch ----
__global__ void k_final(const float* __restrict__ cs_in,
                        const float* __restrict__ avg_in,
                        float* __restrict__ outf) {
    __shared__ float sm[512];
    int t = threadIdx.x;   // 512 threads
    float cnt = (float)g_counts[t];
    g_counts[t] = 0;                              // re-zero for next call
    float ncs = cs_in[t] * 0.99f + 0.01f * cnt;
    outf[OFF_NCS + t] = ncs;
    sm[t] = ncs;
    __syncthreads();
#pragma unroll
    for (int s = 256; s > 0; s >>= 1) {
        if (t < s) sm[t] += sm[t + s];
        __syncthreads();
    }
    float n  = sm[0];
    float cs = (ncs + 1e-5f) / (n + 0.00512f) * n;
#pragma unroll 4
    for (int c = 0; c < C_DIM; c++) {
        float es = g_esum[c * K_DIM + t];
        g_esum[c * K_DIM + t] = 0.0f;             // re-zero for next call
        float av = avg_in[c * K_DIM + t] * 0.99f + 0.01f * es;
        outf[OFF_AVG + c * K_DIM + t] = av;
        outf[OFF_EMB + c * K_DIM + t] = av / cs;
    }
    if (t == 0) {
        outf[OFF_DIFF] = g_diff * (1.0f / 16777216.0f);
        g_diff = 0.0f;                            // re-zero for next call
    }
}

extern "C" void kernel_launch(void* const* d_in, const int* in_sizes, int n_in,
                              void* d_out, int out_size) {
    // Size-based resolution (dict order assumed for the two [C,K] buffers).
    const float* in    = (const float*)d_in[0];
    const float* E     = (const float*)d_in[1];
    const float* csize = (const float*)d_in[2];
    const float* eavg  = (const float*)d_in[3];
    {
        const float* p32k[2] = {nullptr, nullptr};
        int n32k = 0;
        for (int i = 0; i < n_in; i++) {
            if (in_sizes[i] == N_PTS * C_DIM) in = (const float*)d_in[i];
            else if (in_sizes[i] == K_DIM)    csize = (const float*)d_in[i];
            else if (in_sizes[i] == C_DIM * K_DIM && n32k < 2)
                p32k[n32k++] = (const float*)d_in[i];
        }
        if (n32k == 2) { E = p32k[0]; eavg = p32k[1]; }
    }
    float* outf = (float*)d_out;

    const int smem_bytes = (128 * 68 + 512) * sizeof(float);   // 36864
    cudaFuncSetAttribute(k_main, cudaFuncAttributeMaxDynamicSharedMemorySize,
                         smem_bytes);

    k_main<<<2048, 128, smem_bytes>>>(in, E, outf);
    k_final<<<1, 512>>>(csize, eavg, outf);
}

// round 15
// speedup vs baseline: 1.5686x; 1.2371x over previous
#include <cuda_runtime.h>
#include <float.h>

typedef unsigned long long u64;

#define C_DIM 64
#define K_DIM 512
#define N_PTS 262144      // B*H*W

// float32 concat output layout (reference return order):
// out[16777216], diff[1], embedding_ind[262144], new_embedding[32768],
// new_cluster_size[512], new_embedding_avg[32768]
#define OFF_OUT  0
#define OFF_DIFF 16777216
#define OFF_IND  16777217
#define OFF_EMB  17039361
#define OFF_NCS  17072129
#define OFF_AVG  17072641

__device__ float g_esum[C_DIM * K_DIM];  // segment_sum accumulator [C][K]
__device__ int   g_counts[K_DIM];
__device__ float g_diff;
__device__ float g_invcs[K_DIM];         // 1/cs per code

__device__ __forceinline__ u64 ffma2(u64 a, u64 b, u64 c) {
    u64 d;
    asm("fma.rn.f32x2 %0, %1, %2, %3;" : "=l"(d) : "l"(a), "l"(b), "l"(c));
    return d;
}

// ---------------- zero scratch (inside graph -> every replay) ----------------
__global__ void k_zero() {
    int i = blockIdx.x * 256 + threadIdx.x;   // grid 130 x 256
    if (i < C_DIM * K_DIM) g_esum[i] = 0.0f;
    int j = i - C_DIM * K_DIM;
    if (j >= 0 && j < K_DIM) g_counts[j] = 0;
    if (i == 0) g_diff = 0.0f;
}

// ---------------- main: argmin + quantize + diff + EMA scatter ----------------
// 128 threads/CTA, 2 points/thread (each channel-packed f32x2), 256 pts/CTA,
// grid 1024, 3 CTAs/SM (12 warps). One broadcast LDS.128 feeds 4 FFMA2.
// smem: 128-code chunk, rows of 68 floats (272B, 16B-aligned) + ee[512].
__global__ void __launch_bounds__(128, 3)
k_main(const float* __restrict__ in, const float* __restrict__ E,
       float* __restrict__ outf) {
    extern __shared__ float sefl[];              // [128*68] codes, then ee[512]
    ulonglong2* se4 = (ulonglong2*)sefl;         // row stride 17 ull2
    float* see = sefl + 128 * 68;                // ||e_k||^2

    const int tid  = threadIdx.x;
    const int base = blockIdx.x * 256;           // 256 points per CTA
    const int b    = base >> 12;
    const int hw0  = (base & 4095) + tid;        // point A
    const int nA   = base + tid;
    const int nB   = nA + 128;                   // point B (same b: 4096%256==0)

    // ---- load 2 points, channels packed f32x2 (coalesced LDG.32) ----
    const float* __restrict__ xa = in + (size_t)b * 262144 + hw0;
    const float* __restrict__ xb = xa + 128;
    u64 x2a[32], x2b[32];
#pragma unroll
    for (int j = 0; j < 32; j++) {
        float a0 = xa[(size_t)(2 * j)     * 4096];
        float a1 = xa[(size_t)(2 * j + 1) * 4096];
        asm("mov.b64 %0, {%1, %2};" : "=l"(x2a[j]) : "f"(a0), "f"(a1));
        float b0 = xb[(size_t)(2 * j)     * 4096];
        float b1 = xb[(size_t)(2 * j + 1) * 4096];
        asm("mov.b64 %0, {%1, %2};" : "=l"(x2b[j]) : "f"(b0), "f"(b1));
    }
    u64 xsa = 0ULL, xsb = 0ULL;
#pragma unroll
    for (int j = 0; j < 32; j++) {
        xsa = ffma2(x2a[j], x2a[j], xsa);
        xsb = ffma2(x2b[j], x2b[j], xsb);
    }
    float lo, hi;
    asm("mov.b64 {%0, %1}, %2;" : "=f"(lo), "=f"(hi) : "l"(xsa));
    const float xxa = lo + hi;
    asm("mov.b64 {%0, %1}, %2;" : "=f"(lo), "=f"(hi) : "l"(xsb));
    const float xxb = lo + hi;

    // ---- per-CTA ||e_k||^2 into smem (covered by first chunk's barrier) ----
    for (int k = tid; k < K_DIM; k += 128) {
        float s = 0.0f;
#pragma unroll
        for (int c = 0; c < C_DIM; c++) {
            float v = E[c * K_DIM + k];
            s = fmaf(v, v, s);
        }
        see[k] = s;
    }

    float bestA = FLT_MAX, bestB = FLT_MAX;
    int   biA = 0, biB = 0;

#pragma unroll 1
    for (int chunk = 0; chunk < 4; ++chunk) {
        const int kc0 = chunk * 128;
        __syncthreads();
        // stage 128 codes x 64 channels (coalesced E reads; rows of 68 floats)
        for (int idx = tid; idx < 128 * C_DIM; idx += 128) {
            int c = idx >> 7, k = idx & 127;
            sefl[k * 68 + c] = E[c * K_DIM + kc0 + k];
        }
        __syncthreads();

#pragma unroll 1
        for (int kq = 0; kq < 128; kq += 2) {
            const ulonglong2* __restrict__ r0 = se4 + kq * 17;
            const ulonglong2* __restrict__ r1 = r0 + 17;
            u64 aA0 = 0ULL, aA1 = 0ULL, aB0 = 0ULL, aB1 = 0ULL;
#pragma unroll
            for (int cq = 0; cq < 16; cq++) {       // 4 channels per ull2
                ulonglong2 e0 = r0[cq];             // broadcast LDS.128
                ulonglong2 e1 = r1[cq];
                aA0 = ffma2(x2a[2 * cq],     e0.x, aA0);
                aB0 = ffma2(x2b[2 * cq],     e0.x, aB0);
                aA1 = ffma2(x2a[2 * cq],     e1.x, aA1);
                aB1 = ffma2(x2b[2 * cq],     e1.x, aB1);
                aA0 = ffma2(x2a[2 * cq + 1], e0.y, aA0);
                aB0 = ffma2(x2b[2 * cq + 1], e0.y, aB0);
                aA1 = ffma2(x2a[2 * cq + 1], e1.y, aA1);
                aB1 = ffma2(x2b[2 * cq + 1], e1.y, aB1);
            }
            float eev0 = see[kc0 + kq];
            float eev1 = see[kc0 + kq + 1];
            asm("mov.b64 {%0, %1}, %2;" : "=f"(lo), "=f"(hi) : "l"(aA0));
            float dA0 = fmaf(-2.0f, lo + hi, xxa) + eev0;
            asm("mov.b64 {%0, %1}, %2;" : "=f"(lo), "=f"(hi) : "l"(aA1));
            float dA1 = fmaf(-2.0f, lo + hi, xxa) + eev1;
            asm("mov.b64 {%0, %1}, %2;" : "=f"(lo), "=f"(hi) : "l"(aB0));
            float dB0 = fmaf(-2.0f, lo + hi, xxb) + eev0;
            asm("mov.b64 {%0, %1}, %2;" : "=f"(lo), "=f"(hi) : "l"(aB1));
            float dB1 = fmaf(-2.0f, lo + hi, xxb) + eev1;
            if (dA0 < bestA) { bestA = dA0; biA = kc0 + kq; }
            if (dA1 < bestA) { bestA = dA1; biA = kc0 + kq + 1; }
            if (dB0 < bestB) { bestB = dB0; biB = kc0 + kq; }
            if (dB1 < bestB) { bestB = dB1; biB = kc0 + kq + 1; }
        }
    }

    // ---- fused epilogue: quantize_st output, diff partial, segment_sum ----
    float* __restrict__ outA = outf + OFF_OUT + (size_t)b * 262144 + hw0;
    float* __restrict__ outB = outA + 128;
    const float* __restrict__ EbA = E + biA;
    const float* __restrict__ EbB = E + biB;
    float dsum = 0.0f;
#pragma unroll 4
    for (int j = 0; j < 32; j++) {
        float xv0, xv1, yv0, yv1;
        asm("mov.b64 {%0, %1}, %2;" : "=f"(xv0), "=f"(xv1) : "l"(x2a[j]));
        asm("mov.b64 {%0, %1}, %2;" : "=f"(yv0), "=f"(yv1) : "l"(x2b[j]));
        int c0 = 2 * j, c1 = 2 * j + 1;
        float qa0 = EbA[(size_t)c0 * K_DIM], qa1 = EbA[(size_t)c1 * K_DIM];
        float qb0 = EbB[(size_t)c0 * K_DIM], qb1 = EbB[(size_t)c1 * K_DIM];
        float ta0 = qa0 - xv0, ta1 = qa1 - xv1;
        float tb0 = qb0 - yv0, tb1 = qb1 - yv1;
        outA[(size_t)c0 * 4096] = xv0 + ta0;       // x + (q - x), ref rounding
        outA[(size_t)c1 * 4096] = xv1 + ta1;
        outB[(size_t)c0 * 4096] = yv0 + tb0;
        outB[(size_t)c1 * 4096] = yv1 + tb1;
        dsum = fmaf(ta0, ta0, dsum); dsum = fmaf(ta1, ta1, dsum);
        dsum = fmaf(tb0, tb0, dsum); dsum = fmaf(tb1, tb1, dsum);
        atomicAdd(&g_esum[c0 * K_DIM + biA], xv0);
        atomicAdd(&g_esum[c1 * K_DIM + biA], xv1);
        atomicAdd(&g_esum[c0 * K_DIM + biB], yv0);
        atomicAdd(&g_esum[c1 * K_DIM + biB], yv1);
    }
    atomicAdd(&g_counts[biA], 1);
    atomicAdd(&g_counts[biB], 1);
    outf[OFF_IND + nA] = (float)biA;
    outf[OFF_IND + nB] = (float)biB;

    // diff block reduction (4 warps)
    __syncthreads();
#pragma unroll
    for (int o = 16; o; o >>= 1) dsum += __shfl_down_sync(0xffffffffu, dsum, o);
    if ((tid & 31) == 0) sefl[tid >> 5] = dsum;
    __syncthreads();
    if (tid == 0)
        atomicAdd(&g_diff, sefl[0] + sefl[1] + sefl[2] + sefl[3]);
}

// ---------------- ncs: EMA counts, n-reduction, 1/cs table, diff ----------------
__global__ void k_ncs(const float* __restrict__ cs_in, float* __restrict__ outf) {
    __shared__ float sm[512];
    int t = threadIdx.x;   // 512 threads
    float cnt = (float)g_counts[t];
    float ncs = cs_in[t] * 0.99f + 0.01f * cnt;
    outf[OFF_NCS + t] = ncs;
    sm[t] = ncs;
    __syncthreads();
#pragma unroll
    for (int s = 256; s > 0; s >>= 1) {
        if (t < s) sm[t] += sm[t + s];
        __syncthreads();
    }
    float n  = sm[0];
    float cs = (ncs + 1e-5f) / (n + 0.00512f) * n;
    g_invcs[t] = 1.0f / cs;
    if (t == 0) outf[OFF_DIFF] = g_diff * (1.0f / 16777216.0f);
}

// ---------------- emb: parallel EMA avg + normalized embedding ----------------
__global__ void k_emb(const float* __restrict__ avg_in, float* __restrict__ outf) {
    int c = blockIdx.x;          // 64 blocks
    int t = threadIdx.x;         // 512 threads
    int idx = c * K_DIM + t;
    float av = avg_in[idx] * 0.99f + 0.01f * g_esum[idx];
    outf[OFF_AVG + idx] = av;
    outf[OFF_EMB + idx] = av * g_invcs[t];
}

extern "C" void kernel_launch(void* const* d_in, const int* in_sizes, int n_in,
                              void* d_out, int out_size) {
    // Size-based resolution (dict order assumed for the two [C,K] buffers).
    const float* in    = (const float*)d_in[0];
    const float* E     = (const float*)d_in[1];
    const float* csize = (const float*)d_in[2];
    const float* eavg  = (const float*)d_in[3];
    {
        const float* p32k[2] = {nullptr, nullptr};
        int n32k = 0;
        for (int i = 0; i < n_in; i++) {
            if (in_sizes[i] == N_PTS * C_DIM) in = (const float*)d_in[i];
            else if (in_sizes[i] == K_DIM)    csize = (const float*)d_in[i];
            else if (in_sizes[i] == C_DIM * K_DIM && n32k < 2)
                p32k[n32k++] = (const float*)d_in[i];
        }
        if (n32k == 2) { E = p32k[0]; eavg = p32k[1]; }
    }
    float* outf = (float*)d_out;

    const int smem_bytes = (128 * 68 + 512) * sizeof(float);   // 36864
    cudaFuncSetAttribute(k_main, cudaFuncAttributeMaxDynamicSharedMemorySize,
                         smem_bytes);

    k_zero<<<130, 256>>>();
    k_main<<<1024, 128, smem_bytes>>>(in, E, outf);
    k_ncs<<<1, 512>>>(csize, outf);
    k_emb<<<64, 512>>>(eavg, outf);
}